// round 10
// baseline (speedup 1.0000x reference)
#include <cuda_runtime.h>
#include <cuda_bf16.h>
#include <cstdint>

#define BATCH  4
#define LSEQ   4096
#define DMODEL 512
#define NST    64
#define TCH    128
#define QCH    32   // LSEQ / TCH
#define KTOT   192  // NST + TCH

#define PAD    68

// ---------------- device scratch ----------------
__device__ float  g_V[TCH * NST];
__device__ float  g_GL[TCH * NST];
__device__ float  g_F2t[TCH * NST];
__device__ float  g_h[TCH];
__device__ float  g_W[TCH * KTOT];           // [t][k] fused weight: [G | Toeplitz(h)]
__device__ float2 g_Mpair[NST * 32];
__device__ float  g_P[(size_t)BATCH * QCH * DMODEL * NST];
__device__ float  g_S[(size_t)BATCH * QCH * DMODEL * NST];

// ---------------- helpers ----------------
__device__ __forceinline__ uint32_t smem_u32(const void* p) {
    uint32_t a;
    asm("{ .reg .u64 t; cvta.to.shared.u64 t, %1; cvt.u32.u64 %0, t; }" : "=r"(a) : "l"(p));
    return a;
}
__device__ __forceinline__ void ldsm_x4(uint32_t* r, uint32_t addr) {
    asm volatile("ldmatrix.sync.aligned.m8n8.x4.shared.b16 {%0,%1,%2,%3}, [%4];"
                 : "=r"(r[0]), "=r"(r[1]), "=r"(r[2]), "=r"(r[3]) : "r"(addr));
}
__device__ __forceinline__ void ldsm_x4_t(uint32_t* r, uint32_t addr) {
    asm volatile("ldmatrix.sync.aligned.m8n8.x4.trans.shared.b16 {%0,%1,%2,%3}, [%4];"
                 : "=r"(r[0]), "=r"(r[1]), "=r"(r[2]), "=r"(r[3]) : "r"(addr));
}
__device__ __forceinline__ void mma16816(float* d, const uint32_t* a, uint32_t b0, uint32_t b1) {
    asm volatile(
        "mma.sync.aligned.m16n8k16.row.col.f32.bf16.bf16.f32 "
        "{%0,%1,%2,%3}, {%4,%5,%6,%7}, {%8,%9}, {%0,%1,%2,%3};"
        : "+f"(d[0]), "+f"(d[1]), "+f"(d[2]), "+f"(d[3])
        : "r"(a[0]), "r"(a[1]), "r"(a[2]), "r"(a[3]), "r"(b0), "r"(b1));
}

// ---------------- precompute (validated, unchanged) ----------------
__global__ __launch_bounds__(1024) void precompute_kernel(
    const float* __restrict__ A, const float* __restrict__ Bv,
    const float* __restrict__ Cv)
{
    __shared__ float sA[64 * 64];
    __shared__ float sAT[64 * PAD];
    __shared__ float scM[64];
    int tid = threadIdx.x;

    for (int idx = tid; idx < 4096; idx += 1024) {
        int i = idx >> 6, j = idx & 63;
        float v = A[idx];
        sA[idx] = v;
        sAT[j * PAD + i] = v;
    }
    if (tid < 64) { g_V[tid] = Bv[tid]; g_GL[tid] = Cv[tid]; }
    __syncthreads();

    int have = 1;
    for (int k = 0; k < 7; k++) {
        for (int idx = tid; idx < have * 16; idx += 1024) {
            int m = idx >> 4, n0 = (idx & 15) * 4;
            const float* vrow = &g_V[m * 64];
            const float* grow = &g_GL[m * 64];
            float sv0 = 0.f, sv1 = 0.f, sv2 = 0.f, sv3 = 0.f;
            float sg0 = 0.f, sg1 = 0.f, sg2 = 0.f, sg3 = 0.f;
            #pragma unroll 8
            for (int j = 0; j < 64; j++) {
                float av = vrow[j], ag = grow[j];
                float4 ta = *(const float4*)&sAT[j * PAD + n0];
                float4 tb = *(const float4*)&sA[j * 64 + n0];
                sv0 += av * ta.x; sv1 += av * ta.y; sv2 += av * ta.z; sv3 += av * ta.w;
                sg0 += ag * tb.x; sg1 += ag * tb.y; sg2 += ag * tb.z; sg3 += ag * tb.w;
            }
            *(float4*)&g_V[(m + have) * 64 + n0]  = make_float4(sv0, sv1, sv2, sv3);
            *(float4*)&g_GL[(m + have) * 64 + n0] = make_float4(sg0, sg1, sg2, sg3);
        }

        int i  = tid >> 4;
        int j0 = (tid & 15) * 4;
        float o0 = 0.f, o1 = 0.f, o2 = 0.f, o3 = 0.f;
        #pragma unroll 8
        for (int l = 0; l < 64; l++) {
            float a = sA[i * 64 + l];
            float4 b4 = *(const float4*)&sA[l * 64 + j0];
            o0 += a * b4.x; o1 += a * b4.y; o2 += a * b4.z; o3 += a * b4.w;
        }
        __syncthreads();
        sAT[(j0 + 0) * PAD + i] = o0;
        sAT[(j0 + 1) * PAD + i] = o1;
        sAT[(j0 + 2) * PAD + i] = o2;
        sAT[(j0 + 3) * PAD + i] = o3;
        __syncthreads();
        for (int idx = tid; idx < 4096; idx += 1024) {
            int i2 = idx >> 6, j2 = idx & 63;
            sA[idx] = sAT[j2 * PAD + i2];
        }
        __syncthreads();
        have <<= 1;
    }
    // sA = M = A^128

    for (int idx = tid; idx < NST * 32; idx += 1024) {
        int mm = idx >> 5, lane = idx & 31;
        g_Mpair[idx] = make_float2(sAT[mm * PAD + lane], sAT[mm * PAD + lane + 32]);
    }
    for (int idx = tid; idx < TCH * NST; idx += 1024) {
        int t = idx >> 6, n = idx & 63;
        g_F2t[t * 64 + n] = g_V[(127 - t) * 64 + n];
    }
    if (tid < 64) {  // cM = c * A^128
        float s = 0.f;
        #pragma unroll 8
        for (int j = 0; j < 64; j++) s += g_GL[j] * sA[j * 64 + tid];
        scM[tid] = s;
    }
    if (tid < 128) { // h[m] = c A^m b
        float s = 0.f;
        #pragma unroll 8
        for (int n = 0; n < 64; n++) s += g_GL[n] * g_V[tid * 64 + n];
        g_h[tid] = s;
    }
    __syncthreads();
    // W[t][k]: k<64 -> (c A^{t+1})[k];  k>=64 -> h[t-(k-64)] (lower-tri)
    for (int idx = tid; idx < TCH * KTOT; idx += 1024) {
        int t = idx / KTOT, k = idx % KTOT;
        float w;
        if (k < NST) w = (t < 127) ? g_GL[(t + 1) * 64 + k] : scM[k];
        else { int j = k - NST; w = (t >= j) ? g_h[t - j] : 0.f; }
        g_W[idx] = w;
    }
}

// ---------------- stage A (validated, unchanged) ----------------
__global__ __launch_bounds__(256) void stageA_kernel(const float* __restrict__ U)
{
    int bq = blockIdx.x;
    int b = bq >> 5, q = bq & 31;
    int col0 = blockIdx.y << 6;
    int tid = threadIdx.x;
    int tx = tid & 15, ty = tid >> 4;

    __shared__ float sA[32][64];
    __shared__ float sB[32][64];
    __shared__ float sT[64][65];

    float acc[4][4] = {};
    const float* Ubase = U + ((size_t)b * LSEQ + (size_t)q * TCH) * DMODEL + col0;

    for (int kk = 0; kk < TCH; kk += 32) {
        #pragma unroll
        for (int p = 0; p < 8; p++) {
            int idx = tid + p * 256;
            int k = idx >> 6, n = idx & 63;
            sA[k][n] = g_F2t[(kk + k) * 64 + n];
            sB[k][n] = Ubase[(size_t)(kk + k) * DMODEL + n];
        }
        __syncthreads();
        #pragma unroll
        for (int k = 0; k < 32; k++) {
            float a[4], bb[4];
            *(float4*)a  = *(const float4*)&sA[k][ty * 4];
            *(float4*)bb = *(const float4*)&sB[k][tx * 4];
            #pragma unroll
            for (int r = 0; r < 4; r++)
                #pragma unroll
                for (int c = 0; c < 4; c++)
                    acc[r][c] += a[r] * bb[c];
        }
        __syncthreads();
    }

    #pragma unroll
    for (int r = 0; r < 4; r++)
        #pragma unroll
        for (int c = 0; c < 4; c++)
            sT[ty * 4 + r][tx * 4 + c] = acc[r][c];
    __syncthreads();

    float* Pb = g_P + ((size_t)(b * QCH + q) * DMODEL + col0) * NST;
    #pragma unroll
    for (int p = 0; p < 16; p++) {
        int idx = tid + p * 256;
        int c = idx >> 6, n = idx & 63;
        Pb[(size_t)c * NST + n] = sT[n][c];
    }
}

// ---------------- stage B (validated, unchanged) ----------------
__global__ __launch_bounds__(256) void stageB_kernel()
{
    __shared__ float2 sM2[NST * 32];
    int tid = threadIdx.x;
    for (int i = tid; i < NST * 32; i += 256) sM2[i] = g_Mpair[i];
    __syncthreads();

    int warp = tid >> 5, lane = tid & 31;
    int col = blockIdx.x * 8 + warp;
    int b = col >> 9, d = col & 511;

    float s0 = 0.f, s1 = 0.f;
    for (int q = 0; q < QCH; q++) {
        size_t off = ((size_t)(b * QCH + q) * DMODEL + d) * NST;
        g_S[off + lane]      = s0;
        g_S[off + 32 + lane] = s1;
        float p0 = g_P[off + lane];
        float p1 = g_P[off + 32 + lane];
        float a0 = 0.f, a1 = 0.f;
        #pragma unroll
        for (int mm = 0; mm < 32; mm++) {
            float v = __shfl_sync(0xffffffffu, s0, mm);
            float2 m2 = sM2[mm * 32 + lane];
            a0 += m2.x * v;
            a1 += m2.y * v;
        }
        #pragma unroll
        for (int mm = 0; mm < 32; mm++) {
            float v = __shfl_sync(0xffffffffu, s1, mm);
            float2 m2 = sM2[(mm + 32) * 32 + lane];
            a0 += m2.x * v;
            a1 += m2.y * v;
        }
        s0 = a0 + p0; s1 = a1 + p1;
    }
}

// ---------------- stage C: mma.sync bf16-split (portable PTX) ----------------
// smem layout (bytes):
#define WSTR  200   // W row stride in bf16 (400B: ldmatrix conflict-free, 16B aligned)
#define XSTR  72    // S/U row stride in bf16 (144B)
#define SW_HI 0
#define SW_LO 51200                       // 128*200*2
#define SS_HI 102400
#define SS_LO (SS_HI + 9216)              // 64*72*2
#define SU_HI (SS_HI + 18432)
#define SU_LO (SU_HI + 18432)             // 128*72*2
#define C_SMEM (SU_LO + 18432)            // 157696

__global__ __launch_bounds__(256) void stageC_kernel(const float* __restrict__ U,
                                                     float* __restrict__ Y)
{
    extern __shared__ char smem[];
    uint32_t sb = smem_u32(smem);
    __nv_bfloat16* Whi = (__nv_bfloat16*)(smem + SW_HI);
    __nv_bfloat16* Wlo = (__nv_bfloat16*)(smem + SW_LO);
    __nv_bfloat16* Shi = (__nv_bfloat16*)(smem + SS_HI);
    __nv_bfloat16* Slo = (__nv_bfloat16*)(smem + SS_LO);
    __nv_bfloat16* Uhi = (__nv_bfloat16*)(smem + SU_HI);
    __nv_bfloat16* Ulo = (__nv_bfloat16*)(smem + SU_LO);

    int tid = threadIdx.x, lane = tid & 31, wid = tid >> 5;
    int bq = blockIdx.x, b = bq >> 5, q = bq & 31;

    // convert W once (fp32 -> bf16 hi/lo)
    for (int idx = tid; idx < TCH * KTOT; idx += 256) {
        int t = idx / KTOT, k = idx - t * KTOT;
        float v = g_W[idx];
        __nv_bfloat16 hi = __float2bfloat16(v);
        __nv_bfloat16 lo = __float2bfloat16(v - __bfloat162float(hi));
        Whi[t * WSTR + k] = hi;
        Wlo[t * WSTR + k] = lo;
    }

    int wr = wid >> 1, wc = wid & 1;
    int row0 = wr * 32, nb = wc * 32;
    uint32_t sel = lane >> 3, li = lane & 7;
    // ldmatrix per-lane offsets (element units)
    uint32_t a_row  = ((sel & 1) << 3) + li,  a_col  = (sel >> 1) << 3;  // A (W, non-trans)
    uint32_t bs_row = ((sel >> 1) << 3) + li, bs_col = (sel & 1) << 3;   // B from S (non-trans)
    uint32_t bu_row = ((sel & 1) << 3) + li,  bu_col = (sel >> 1) << 3;  // B from U (trans)

    const float* Ubq = U + ((size_t)b * LSEQ + (size_t)q * TCH) * DMODEL;
    float* Ybq = Y + ((size_t)b * LSEQ + (size_t)q * TCH) * DMODEL;
    const float* Sbq = g_S + (size_t)(b * QCH + q) * DMODEL * NST;

    #pragma unroll 1
    for (int ct = 0; ct < 8; ct++) {
        int col0 = ct << 6;

        // ---- build B tiles (coalesced LDG, conflict-free STS) ----
        const float* Sb = Sbq + (size_t)col0 * NST;
        #pragma unroll 1
        for (int idx = tid; idx < 64 * 64; idx += 256) {
            int c = idx >> 6, k = idx & 63;
            float v = Sb[idx];
            __nv_bfloat16 hi = __float2bfloat16(v);
            __nv_bfloat16 lo = __float2bfloat16(v - __bfloat162float(hi));
            Shi[c * XSTR + k] = hi;
            Slo[c * XSTR + k] = lo;
        }
        #pragma unroll 1
        for (int idx = tid; idx < 128 * 64; idx += 256) {
            int t = idx >> 6, c = idx & 63;
            float v = Ubq[(size_t)t * DMODEL + col0 + c];
            __nv_bfloat16 hi = __float2bfloat16(v);
            __nv_bfloat16 lo = __float2bfloat16(v - __bfloat162float(hi));
            Uhi[t * XSTR + c] = hi;
            Ulo[t * XSTR + c] = lo;
        }
        __syncthreads();

        float acc[2][4][4] = {};

        // ---- S part: k = 0..63 (4 k16 steps, non-trans B) ----
        #pragma unroll
        for (int ks = 0; ks < 4; ks++) {
            int kk = ks * 16;
            uint32_t ah[2][4], al[2][4], bh[2][4], bl[2][4];
            #pragma unroll
            for (int am = 0; am < 2; am++) {
                uint32_t off = ((row0 + am * 16 + a_row) * WSTR + kk + a_col) * 2;
                ldsm_x4(ah[am], sb + SW_HI + off);
                ldsm_x4(al[am], sb + SW_LO + off);
            }
            #pragma unroll
            for (int pp = 0; pp < 2; pp++) {
                uint32_t off = ((nb + pp * 16 + bs_row) * XSTR + kk + bs_col) * 2;
                ldsm_x4(bh[pp], sb + SS_HI + off);
                ldsm_x4(bl[pp], sb + SS_LO + off);
            }
            #pragma unroll
            for (int am = 0; am < 2; am++)
                #pragma unroll
                for (int nt = 0; nt < 4; nt++) {
                    uint32_t b0h = bh[nt >> 1][(nt & 1) * 2], b1h = bh[nt >> 1][(nt & 1) * 2 + 1];
                    uint32_t b0l = bl[nt >> 1][(nt & 1) * 2], b1l = bl[nt >> 1][(nt & 1) * 2 + 1];
                    mma16816(acc[am][nt], ah[am], b0h, b1h);
                    mma16816(acc[am][nt], ah[am], b0l, b1l);
                    mma16816(acc[am][nt], al[am], b0h, b1h);
                }
        }

        // ---- U part: k = 64..191 (8 k16 steps, trans B) ----
        #pragma unroll
        for (int ks = 4; ks < 12; ks++) {
            int kk = ks * 16;          // A col base
            int t0 = kk - 64;          // U row base
            uint32_t ah[2][4], al[2][4], bh[2][4], bl[2][4];
            #pragma unroll
            for (int am = 0; am < 2; am++) {
                uint32_t off = ((row0 + am * 16 + a_row) * WSTR + kk + a_col) * 2;
                ldsm_x4(ah[am], sb + SW_HI + off);
                ldsm_x4(al[am], sb + SW_LO + off);
            }
            #pragma unroll
            for (int pp = 0; pp < 2; pp++) {
                uint32_t off = ((t0 + bu_row) * XSTR + nb + pp * 16 + bu_col) * 2;
                ldsm_x4_t(bh[pp], sb + SU_HI + off);
                ldsm_x4_t(bl[pp], sb + SU_LO + off);
            }
            #pragma unroll
            for (int am = 0; am < 2; am++)
                #pragma unroll
                for (int nt = 0; nt < 4; nt++) {
                    uint32_t b0h = bh[nt >> 1][(nt & 1) * 2], b1h = bh[nt >> 1][(nt & 1) * 2 + 1];
                    uint32_t b0l = bl[nt >> 1][(nt & 1) * 2], b1l = bl[nt >> 1][(nt & 1) * 2 + 1];
                    mma16816(acc[am][nt], ah[am], b0h, b1h);
                    mma16816(acc[am][nt], ah[am], b0l, b1l);
                    mma16816(acc[am][nt], al[am], b0h, b1h);
                }
        }
        __syncthreads();   // all ldmatrix reads done before next tile's build

        // ---- epilogue: direct float2 stores from C fragments ----
        int gid = lane >> 2, tig = lane & 3;
        #pragma unroll
        for (int am = 0; am < 2; am++)
            #pragma unroll
            for (int nt = 0; nt < 4; nt++) {
                int row = row0 + am * 16 + gid;
                int col = col0 + nb + nt * 8 + tig * 2;
                *(float2*)&Ybq[(size_t)row * DMODEL + col] =
                    make_float2(acc[am][nt][0], acc[am][nt][1]);
                *(float2*)&Ybq[(size_t)(row + 8) * DMODEL + col] =
                    make_float2(acc[am][nt][2], acc[am][nt][3]);
            }
    }
}

// ---------------- launch ----------------
extern "C" void kernel_launch(void* const* d_in, const int* in_sizes, int n_in,
                              void* d_out, int out_size)
{
    const float* u  = (const float*)d_in[0];
    const float* A  = (const float*)d_in[1];
    const float* Bv = (const float*)d_in[2];
    const float* Cv = (const float*)d_in[3];
    float* y = (float*)d_out;

    cudaFuncSetAttribute(stageC_kernel,
                         cudaFuncAttributeMaxDynamicSharedMemorySize, C_SMEM);

    precompute_kernel<<<1, 1024>>>(A, Bv, Cv);

    dim3 grid(BATCH * QCH, DMODEL / 64);
    stageA_kernel<<<grid, 256>>>(u);
    stageB_kernel<<<256, 256>>>();
    stageC_kernel<<<BATCH * QCH, 256, C_SMEM>>>(u, y);
}

// round 13
// speedup vs baseline: 1.6607x; 1.6607x over previous
#include <cuda_runtime.h>
#include <cuda_bf16.h>
#include <cstdint>

#define BATCH  4
#define LSEQ   4096
#define DMODEL 512
#define NST    64
#define TCH    128
#define QCH    32   // LSEQ / TCH
#define KTOT   192  // NST + TCH

#define PAD    68

// ---------------- device scratch ----------------
__device__ float  g_V[TCH * NST];
__device__ float  g_GL[TCH * NST];
__device__ float  g_F2t[TCH * NST];
__device__ float  g_h[TCH];
__device__ float  g_W[TCH * KTOT];           // [t][k] fused weight: [G | Toeplitz(h)]
__device__ float2 g_Mpair[NST * 32];
__device__ float  g_P[(size_t)BATCH * QCH * DMODEL * NST];
__device__ float  g_S[(size_t)BATCH * QCH * DMODEL * NST];

// ---------------- helpers ----------------
__device__ __forceinline__ uint32_t smem_u32(const void* p) {
    uint32_t a;
    asm("{ .reg .u64 t; cvta.to.shared.u64 t, %1; cvt.u32.u64 %0, t; }" : "=r"(a) : "l"(p));
    return a;
}
__device__ __forceinline__ void ldsm_x4(uint32_t* r, uint32_t addr) {
    asm volatile("ldmatrix.sync.aligned.m8n8.x4.shared.b16 {%0,%1,%2,%3}, [%4];"
                 : "=r"(r[0]), "=r"(r[1]), "=r"(r[2]), "=r"(r[3]) : "r"(addr));
}
__device__ __forceinline__ void ldsm_x4_t(uint32_t* r, uint32_t addr) {
    asm volatile("ldmatrix.sync.aligned.m8n8.x4.trans.shared.b16 {%0,%1,%2,%3}, [%4];"
                 : "=r"(r[0]), "=r"(r[1]), "=r"(r[2]), "=r"(r[3]) : "r"(addr));
}
__device__ __forceinline__ void mma16816(float* d, const uint32_t* a, uint32_t b0, uint32_t b1) {
    asm volatile(
        "mma.sync.aligned.m16n8k16.row.col.f32.bf16.bf16.f32 "
        "{%0,%1,%2,%3}, {%4,%5,%6,%7}, {%8,%9}, {%0,%1,%2,%3};"
        : "+f"(d[0]), "+f"(d[1]), "+f"(d[2]), "+f"(d[3])
        : "r"(a[0]), "r"(a[1]), "r"(a[2]), "r"(a[3]), "r"(b0), "r"(b1));
}
// pack 2 floats -> bf16x2 hi pair + bf16x2 lo (residual) pair
__device__ __forceinline__ void pack_hilo(float a, float b, uint32_t& hi, uint32_t& lo) {
    __nv_bfloat162 h = __floats2bfloat162_rn(a, b);
    float ra = a - __bfloat162float(h.x);
    float rb = b - __bfloat162float(h.y);
    __nv_bfloat162 l = __floats2bfloat162_rn(ra, rb);
    hi = *(uint32_t*)&h;
    lo = *(uint32_t*)&l;
}

// ---------------- precompute (validated, unchanged) ----------------
__global__ __launch_bounds__(1024) void precompute_kernel(
    const float* __restrict__ A, const float* __restrict__ Bv,
    const float* __restrict__ Cv)
{
    __shared__ float sA[64 * 64];
    __shared__ float sAT[64 * PAD];
    __shared__ float scM[64];
    int tid = threadIdx.x;

    for (int idx = tid; idx < 4096; idx += 1024) {
        int i = idx >> 6, j = idx & 63;
        float v = A[idx];
        sA[idx] = v;
        sAT[j * PAD + i] = v;
    }
    if (tid < 64) { g_V[tid] = Bv[tid]; g_GL[tid] = Cv[tid]; }
    __syncthreads();

    int have = 1;
    for (int k = 0; k < 7; k++) {
        for (int idx = tid; idx < have * 16; idx += 1024) {
            int m = idx >> 4, n0 = (idx & 15) * 4;
            const float* vrow = &g_V[m * 64];
            const float* grow = &g_GL[m * 64];
            float sv0 = 0.f, sv1 = 0.f, sv2 = 0.f, sv3 = 0.f;
            float sg0 = 0.f, sg1 = 0.f, sg2 = 0.f, sg3 = 0.f;
            #pragma unroll 8
            for (int j = 0; j < 64; j++) {
                float av = vrow[j], ag = grow[j];
                float4 ta = *(const float4*)&sAT[j * PAD + n0];
                float4 tb = *(const float4*)&sA[j * 64 + n0];
                sv0 += av * ta.x; sv1 += av * ta.y; sv2 += av * ta.z; sv3 += av * ta.w;
                sg0 += ag * tb.x; sg1 += ag * tb.y; sg2 += ag * tb.z; sg3 += ag * tb.w;
            }
            *(float4*)&g_V[(m + have) * 64 + n0]  = make_float4(sv0, sv1, sv2, sv3);
            *(float4*)&g_GL[(m + have) * 64 + n0] = make_float4(sg0, sg1, sg2, sg3);
        }

        int i  = tid >> 4;
        int j0 = (tid & 15) * 4;
        float o0 = 0.f, o1 = 0.f, o2 = 0.f, o3 = 0.f;
        #pragma unroll 8
        for (int l = 0; l < 64; l++) {
            float a = sA[i * 64 + l];
            float4 b4 = *(const float4*)&sA[l * 64 + j0];
            o0 += a * b4.x; o1 += a * b4.y; o2 += a * b4.z; o3 += a * b4.w;
        }
        __syncthreads();
        sAT[(j0 + 0) * PAD + i] = o0;
        sAT[(j0 + 1) * PAD + i] = o1;
        sAT[(j0 + 2) * PAD + i] = o2;
        sAT[(j0 + 3) * PAD + i] = o3;
        __syncthreads();
        for (int idx = tid; idx < 4096; idx += 1024) {
            int i2 = idx >> 6, j2 = idx & 63;
            sA[idx] = sAT[j2 * PAD + i2];
        }
        __syncthreads();
        have <<= 1;
    }
    // sA = M = A^128

    for (int idx = tid; idx < NST * 32; idx += 1024) {
        int mm = idx >> 5, lane = idx & 31;
        g_Mpair[idx] = make_float2(sAT[mm * PAD + lane], sAT[mm * PAD + lane + 32]);
    }
    for (int idx = tid; idx < TCH * NST; idx += 1024) {
        int t = idx >> 6, n = idx & 63;
        g_F2t[t * 64 + n] = g_V[(127 - t) * 64 + n];
    }
    if (tid < 64) {  // cM = c * A^128
        float s = 0.f;
        #pragma unroll 8
        for (int j = 0; j < 64; j++) s += g_GL[j] * sA[j * 64 + tid];
        scM[tid] = s;
    }
    if (tid < 128) { // h[m] = c A^m b
        float s = 0.f;
        #pragma unroll 8
        for (int n = 0; n < 64; n++) s += g_GL[n] * g_V[tid * 64 + n];
        g_h[tid] = s;
    }
    __syncthreads();
    // W[t][k]: k<64 -> (c A^{t+1})[k];  k>=64 -> h[t-(k-64)] (lower-tri)
    for (int idx = tid; idx < TCH * KTOT; idx += 1024) {
        int t = idx / KTOT, k = idx % KTOT;
        float w;
        if (k < NST) w = (t < 127) ? g_GL[(t + 1) * 64 + k] : scM[k];
        else { int j = k - NST; w = (t >= j) ? g_h[t - j] : 0.f; }
        g_W[idx] = w;
    }
}

// ---------------- stage A (validated, unchanged) ----------------
__global__ __launch_bounds__(256) void stageA_kernel(const float* __restrict__ U)
{
    int bq = blockIdx.x;
    int b = bq >> 5, q = bq & 31;
    int col0 = blockIdx.y << 6;
    int tid = threadIdx.x;
    int tx = tid & 15, ty = tid >> 4;

    __shared__ float sA[32][64];
    __shared__ float sB[32][64];
    __shared__ float sT[64][65];

    float acc[4][4] = {};
    const float* Ubase = U + ((size_t)b * LSEQ + (size_t)q * TCH) * DMODEL + col0;

    for (int kk = 0; kk < TCH; kk += 32) {
        #pragma unroll
        for (int p = 0; p < 8; p++) {
            int idx = tid + p * 256;
            int k = idx >> 6, n = idx & 63;
            sA[k][n] = g_F2t[(kk + k) * 64 + n];
            sB[k][n] = Ubase[(size_t)(kk + k) * DMODEL + n];
        }
        __syncthreads();
        #pragma unroll
        for (int k = 0; k < 32; k++) {
            float a[4], bb[4];
            *(float4*)a  = *(const float4*)&sA[k][ty * 4];
            *(float4*)bb = *(const float4*)&sB[k][tx * 4];
            #pragma unroll
            for (int r = 0; r < 4; r++)
                #pragma unroll
                for (int c = 0; c < 4; c++)
                    acc[r][c] += a[r] * bb[c];
        }
        __syncthreads();
    }

    #pragma unroll
    for (int r = 0; r < 4; r++)
        #pragma unroll
        for (int c = 0; c < 4; c++)
            sT[ty * 4 + r][tx * 4 + c] = acc[r][c];
    __syncthreads();

    float* Pb = g_P + ((size_t)(b * QCH + q) * DMODEL + col0) * NST;
    #pragma unroll
    for (int p = 0; p < 16; p++) {
        int idx = tid + p * 256;
        int c = idx >> 6, n = idx & 63;
        Pb[(size_t)c * NST + n] = sT[n][c];
    }
}

// ---------------- stage B (validated, unchanged) ----------------
__global__ __launch_bounds__(256) void stageB_kernel()
{
    __shared__ float2 sM2[NST * 32];
    int tid = threadIdx.x;
    for (int i = tid; i < NST * 32; i += 256) sM2[i] = g_Mpair[i];
    __syncthreads();

    int warp = tid >> 5, lane = tid & 31;
    int col = blockIdx.x * 8 + warp;
    int b = col >> 9, d = col & 511;

    float s0 = 0.f, s1 = 0.f;
    for (int q = 0; q < QCH; q++) {
        size_t off = ((size_t)(b * QCH + q) * DMODEL + d) * NST;
        g_S[off + lane]      = s0;
        g_S[off + 32 + lane] = s1;
        float p0 = g_P[off + lane];
        float p1 = g_P[off + 32 + lane];
        float a0 = 0.f, a1 = 0.f;
        #pragma unroll
        for (int mm = 0; mm < 32; mm++) {
            float v = __shfl_sync(0xffffffffu, s0, mm);
            float2 m2 = sM2[mm * 32 + lane];
            a0 += m2.x * v;
            a1 += m2.y * v;
        }
        #pragma unroll
        for (int mm = 0; mm < 32; mm++) {
            float v = __shfl_sync(0xffffffffu, s1, mm);
            float2 m2 = sM2[(mm + 32) * 32 + lane];
            a0 += m2.x * v;
            a1 += m2.y * v;
        }
        s0 = a0 + p0; s1 = a1 + p1;
    }
}

// ---------------- stage C: mma.sync bf16-split, register-prefetch pipeline ----------------
// smem layout (bytes):
#define WSTR  200   // W row stride in bf16 (400B: ldmatrix conflict-free, 16B aligned)
#define XSTR  72    // S/U row stride in bf16 (144B)
#define SW_HI 0
#define SW_LO 51200                       // 128*200*2
#define SS_HI 102400
#define SS_LO (SS_HI + 9216)              // 64*72*2
#define SU_HI (SS_HI + 18432)
#define SU_LO (SU_HI + 18432)             // 128*72*2
#define C_SMEM (SU_LO + 18432)            // 157696

__global__ __launch_bounds__(256) void stageC_kernel(const float* __restrict__ U,
                                                     float* __restrict__ Y)
{
    extern __shared__ char smem[];
    uint32_t sb = smem_u32(smem);
    __nv_bfloat16* Whi = (__nv_bfloat16*)(smem + SW_HI);
    __nv_bfloat16* Wlo = (__nv_bfloat16*)(smem + SW_LO);

    int tid = threadIdx.x, lane = tid & 31, wid = tid >> 5;
    int bq = blockIdx.x, b = bq >> 5, q = bq & 31;

    // ---- convert W once: float4 loads (MLP), packed bf16x2 stores ----
    #pragma unroll 4
    for (int i = 0; i < 24; i++) {
        int idx4 = tid + i * 256;                 // 6144 float4 total
        int t = idx4 / 48, k4 = (idx4 % 48) * 4;
        float4 v = *(const float4*)&g_W[idx4 * 4];
        uint32_t h01, l01, h23, l23;
        pack_hilo(v.x, v.y, h01, l01);
        pack_hilo(v.z, v.w, h23, l23);
        *(uint2*)&Whi[t * WSTR + k4] = make_uint2(h01, h23);
        *(uint2*)&Wlo[t * WSTR + k4] = make_uint2(l01, l23);
    }

    int wr = wid >> 1, wc = wid & 1;
    int row0 = wr * 32, nb = wc * 32;
    uint32_t sel = lane >> 3, li = lane & 7;
    // ldmatrix per-lane offsets (element units)
    uint32_t a_row  = ((sel & 1) << 3) + li,  a_col  = (sel >> 1) << 3;  // A (W, non-trans)
    uint32_t bs_row = ((sel >> 1) << 3) + li, bs_col = (sel & 1) << 3;   // B from S (non-trans)
    uint32_t bu_row = ((sel & 1) << 3) + li,  bu_col = (sel >> 1) << 3;  // B from U (trans)

    const float* Ubq = U + ((size_t)b * LSEQ + (size_t)q * TCH) * DMODEL;
    float* Ybq = Y + ((size_t)b * LSEQ + (size_t)q * TCH) * DMODEL;
    const float* Sbq = g_S + (size_t)(b * QCH + q) * DMODEL * NST;

    // per-thread STS coordinates (fixed across tiles)
    int s_c[4], s_k4[4], u_t[8], u_c4[8];
    #pragma unroll
    for (int i = 0; i < 4; i++) { int idx4 = tid + i * 256; s_c[i] = idx4 >> 4; s_k4[i] = (idx4 & 15) << 2; }
    #pragma unroll
    for (int i = 0; i < 8; i++) { int idx4 = tid + i * 256; u_t[i] = idx4 >> 4; u_c4[i] = (idx4 & 15) << 2; }

    // ---- prefetch tile 0 into registers ----
    float4 sreg[4], ureg[8];
    {
        const float* Sb = Sbq;                     // col0 = 0
        #pragma unroll
        for (int i = 0; i < 4; i++) sreg[i] = *(const float4*)&Sb[(tid + i * 256) * 4];
        #pragma unroll
        for (int i = 0; i < 8; i++) ureg[i] = *(const float4*)&Ubq[(size_t)u_t[i] * DMODEL + u_c4[i]];
    }

    #pragma unroll 1
    for (int ct = 0; ct < 8; ct++) {
        int col0 = ct << 6;

        // ---- STS: registers -> bf16 hi/lo smem tiles ----
        #pragma unroll
        for (int i = 0; i < 4; i++) {
            uint32_t h01, l01, h23, l23;
            pack_hilo(sreg[i].x, sreg[i].y, h01, l01);
            pack_hilo(sreg[i].z, sreg[i].w, h23, l23);
            *(uint2*)((__nv_bfloat16*)(smem + SS_HI) + s_c[i] * XSTR + s_k4[i]) = make_uint2(h01, h23);
            *(uint2*)((__nv_bfloat16*)(smem + SS_LO) + s_c[i] * XSTR + s_k4[i]) = make_uint2(l01, l23);
        }
        #pragma unroll
        for (int i = 0; i < 8; i++) {
            uint32_t h01, l01, h23, l23;
            pack_hilo(ureg[i].x, ureg[i].y, h01, l01);
            pack_hilo(ureg[i].z, ureg[i].w, h23, l23);
            *(uint2*)((__nv_bfloat16*)(smem + SU_HI) + u_t[i] * XSTR + u_c4[i]) = make_uint2(h01, h23);
            *(uint2*)((__nv_bfloat16*)(smem + SU_LO) + u_t[i] * XSTR + u_c4[i]) = make_uint2(l01, l23);
        }
        __syncthreads();   // tiles (and W on first iter) visible to all

        // ---- prefetch next tile; LDG latency hides under MMA below ----
        if (ct < 7) {
            int ncol0 = (ct + 1) << 6;
            const float* Sb = Sbq + (size_t)ncol0 * NST;
            #pragma unroll
            for (int i = 0; i < 4; i++) sreg[i] = *(const float4*)&Sb[(tid + i * 256) * 4];
            #pragma unroll
            for (int i = 0; i < 8; i++) ureg[i] = *(const float4*)&Ubq[(size_t)u_t[i] * DMODEL + ncol0 + u_c4[i]];
        }

        float acc[2][4][4] = {};

        // ---- S part: k = 0..63 (4 k16 steps, non-trans B) ----
        #pragma unroll
        for (int ks = 0; ks < 4; ks++) {
            int kk = ks * 16;
            uint32_t ah[2][4], al[2][4], bh[2][4], bl[2][4];
            #pragma unroll
            for (int am = 0; am < 2; am++) {
                uint32_t off = ((row0 + am * 16 + a_row) * WSTR + kk + a_col) * 2;
                ldsm_x4(ah[am], sb + SW_HI + off);
                ldsm_x4(al[am], sb + SW_LO + off);
            }
            #pragma unroll
            for (int pp = 0; pp < 2; pp++) {
                uint32_t off = ((nb + pp * 16 + bs_row) * XSTR + kk + bs_col) * 2;
                ldsm_x4(bh[pp], sb + SS_HI + off);
                ldsm_x4(bl[pp], sb + SS_LO + off);
            }
            #pragma unroll
            for (int am = 0; am < 2; am++)
                #pragma unroll
                for (int nt = 0; nt < 4; nt++) {
                    uint32_t b0h = bh[nt >> 1][(nt & 1) * 2], b1h = bh[nt >> 1][(nt & 1) * 2 + 1];
                    uint32_t b0l = bl[nt >> 1][(nt & 1) * 2], b1l = bl[nt >> 1][(nt & 1) * 2 + 1];
                    mma16816(acc[am][nt], ah[am], b0h, b1h);
                    mma16816(acc[am][nt], ah[am], b0l, b1l);
                    mma16816(acc[am][nt], al[am], b0h, b1h);
                }
        }

        // ---- U part: k = 64..191 (8 k16 steps, trans B) ----
        #pragma unroll
        for (int ks = 4; ks < 12; ks++) {
            int kk = ks * 16;          // A col base
            int t0 = kk - 64;          // U row base
            uint32_t ah[2][4], al[2][4], bh[2][4], bl[2][4];
            #pragma unroll
            for (int am = 0; am < 2; am++) {
                uint32_t off = ((row0 + am * 16 + a_row) * WSTR + kk + a_col) * 2;
                ldsm_x4(ah[am], sb + SW_HI + off);
                ldsm_x4(al[am], sb + SW_LO + off);
            }
            #pragma unroll
            for (int pp = 0; pp < 2; pp++) {
                uint32_t off = ((t0 + bu_row) * XSTR + nb + pp * 16 + bu_col) * 2;
                ldsm_x4_t(bh[pp], sb + SU_HI + off);
                ldsm_x4_t(bl[pp], sb + SU_LO + off);
            }
            #pragma unroll
            for (int am = 0; am < 2; am++)
                #pragma unroll
                for (int nt = 0; nt < 4; nt++) {
                    uint32_t b0h = bh[nt >> 1][(nt & 1) * 2], b1h = bh[nt >> 1][(nt & 1) * 2 + 1];
                    uint32_t b0l = bl[nt >> 1][(nt & 1) * 2], b1l = bl[nt >> 1][(nt & 1) * 2 + 1];
                    mma16816(acc[am][nt], ah[am], b0h, b1h);
                    mma16816(acc[am][nt], ah[am], b0l, b1l);
                    mma16816(acc[am][nt], al[am], b0h, b1h);
                }
        }

        // ---- epilogue: direct float2 stores from C fragments ----
        int gid = lane >> 2, tig = lane & 3;
        #pragma unroll
        for (int am = 0; am < 2; am++)
            #pragma unroll
            for (int nt = 0; nt < 4; nt++) {
                int row = row0 + am * 16 + gid;
                int col = col0 + nb + nt * 8 + tig * 2;
                *(float2*)&Ybq[(size_t)row * DMODEL + col] =
                    make_float2(acc[am][nt][0], acc[am][nt][1]);
                *(float2*)&Ybq[(size_t)(row + 8) * DMODEL + col] =
                    make_float2(acc[am][nt][2], acc[am][nt][3]);
            }
        __syncthreads();   // all ldmatrix reads done before next tile's STS
    }
}

// ---------------- launch ----------------
extern "C" void kernel_launch(void* const* d_in, const int* in_sizes, int n_in,
                              void* d_out, int out_size)
{
    const float* u  = (const float*)d_in[0];
    const float* A  = (const float*)d_in[1];
    const float* Bv = (const float*)d_in[2];
    const float* Cv = (const float*)d_in[3];
    float* y = (float*)d_out;

    cudaFuncSetAttribute(stageC_kernel,
                         cudaFuncAttributeMaxDynamicSharedMemorySize, C_SMEM);

    precompute_kernel<<<1, 1024>>>(A, Bv, Cv);

    dim3 grid(BATCH * QCH, DMODEL / 64);
    stageA_kernel<<<grid, 256>>>(u);
    stageB_kernel<<<256, 256>>>();
    stageC_kernel<<<BATCH * QCH, 256, C_SMEM>>>(u, y);
}